// round 7
// baseline (speedup 1.0000x reference)
#include <cuda_runtime.h>
#include <cuda_bf16.h>
#include <cstdint>

// Problem constants
#define CDIM   256
#define HW     1024             // 32*32
#define KCODE  1024
#define MTILE  64               // z rows per block
#define CBLK   32               // c per block pass
#define NCBLK  (CDIM / CBLK)    // 8
#define KCHUNK 128              // codes per chunk
#define NCHUNK (KCODE / KCHUNK) // 8
#define NTHREADS 128

// dynamic smem (floats):
//   zt  : [CBLK][64] bank-permuted z tile          = 2048 floats
//   etd : 64 code-pair rows x 132 floats (dup e)   = 8448 floats
// epilogue reuses region as eg[32*257] (8224 floats) per half-pass.
#define ZT_FLOATS   (CBLK * 64)           // 2048
#define ETD_STRIDE  132
#define ETD_FLOATS  (64 * ETD_STRIDE)     // 8448
#define SMEM_FLOATS (ZT_FLOATS + ETD_FLOATS)   // 10496
#define SMEM_BYTES  (SMEM_FLOATS * 4)          // 41984 B

__device__ float g_esq[KCODE];

// packed f32x2 FMA: each lane bitwise-identical to fma.rn.f32
__device__ __forceinline__ void ffma2(unsigned long long& acc,
                                      unsigned long long a,
                                      unsigned long long b) {
    asm("fma.rn.f32x2 %0, %1, %2, %0;" : "+l"(acc) : "l"(a), "l"(b));
}
__device__ __forceinline__ void unpack2(unsigned long long v, float& lo, float& hi) {
    asm("mov.b64 {%0, %1}, %2;" : "=f"(lo), "=f"(hi) : "l"(v));
}

// ---------------------------------------------------------------------------
// Kernel 0: e_sq[k] = sum_c emb[k][c]^2, SEQUENTIAL fp32 mul-then-add.
// ---------------------------------------------------------------------------
__global__ void vq_esq_kernel(const float* __restrict__ emb,
                              float* __restrict__ out, int out_size, int nz) {
    int k = blockIdx.x * blockDim.x + threadIdx.x;
    if (k < KCODE) {
        const float* e = emb + (size_t)k * CDIM;
        float s = 0.f;
        #pragma unroll 8
        for (int c = 0; c < CDIM; ++c) {
            float v = e[c];
            s = __fadd_rn(s, __fmul_rn(v, v));
        }
        g_esq[k] = s;
    }
    if (blockIdx.x == 0 && threadIdx.x == 0 && out_size > nz)
        out[nz] = 0.0f;
}

// ---------------------------------------------------------------------------
// Main kernel: 128 threads, 3 CTAs/SM. Per-thread tile 8 rows x 8 codes,
// 8 k-chunks of 128 codes; per chunk 8 c-blocks of 32 c. FFMA2 with
// pre-duplicated e operands; all compute LDS single-wavefront.
//   thread map: tm = tid&7 (rows tm*8..+7), tk = tid>>3 (codes tk*8..+7)
//   zt quad q=m>>2 stored at word (q>>1)*4 + (q&1)*32  (+ (m&3))
//   etd pair kp at row r=(kp&3)*16 + (kp>>2), 4 dup floats per c
// ---------------------------------------------------------------------------
__global__ __launch_bounds__(NTHREADS, 3)
void vq_main_kernel(const float* __restrict__ z,
                    const float* __restrict__ emb,
                    float* __restrict__ out, int out_size, int nz) {
    extern __shared__ float smem[];
    float* zt  = smem;                 // [c*64 + permuted m]
    float* etd = smem + ZT_FLOATS;     // [r*132 + c*4 + q]
    float* eg  = smem;                 // epilogue: [mloc*257 + c]
    __shared__ unsigned long long red[MTILE];
    __shared__ float zsq_sm[MTILE];
    __shared__ float wsum[4];

    const int tid = threadIdx.x;
    const int tm  = tid & 7;           // 8 row groups of 8
    const int tk  = tid >> 3;          // 16 code groups of 8 (per chunk)
    const int b   = blockIdx.x >> 4;
    const int hw0 = (blockIdx.x & 15) * MTILE;

    const float* zbase = z + (size_t)b * CDIM * HW + hw0;

    if (tid < MTILE) { red[tid] = 0xFFFFFFFFFFFFFFFFull; zsq_sm[tid] = 0.f; }

    float best[8];
    int   bidx[8];
    #pragma unroll
    for (int i = 0; i < 8; ++i) { best[i] = 3.4e38f; bidx[i] = 0; }

    for (int chunk = 0; chunk < NCHUNK; ++chunk) {
        unsigned long long acc[4][8];  // [row-pair p][code j]
        #pragma unroll
        for (int p = 0; p < 4; ++p)
            #pragma unroll
            for (int j = 0; j < 8; ++j) acc[p][j] = 0ull;

        for (int blk = 0; blk < NCBLK; ++blk) {
            const int c0 = blk * CBLK;
            __syncthreads();   // prior compute / fold done before refill

            // ---- fill zt: quad m4 -> word (m4>>1)*4 + (m4&1)*32 ------------
            #pragma unroll
            for (int it = 0; it < 4; ++it) {
                int lin = it * NTHREADS + tid;     // 512 float4
                int c   = lin >> 4;
                int m4  = lin & 15;
                float4 v = *(const float4*)(zbase + (size_t)(c0 + c) * HW + m4 * 4);
                int pw = (m4 >> 1) * 4 + (m4 & 1) * 32;
                *(float4*)(zt + c * 64 + pw) = v;
            }

            // ---- fill etd: pair kp = tid>>1, half = tid&1 (16 c each) ------
            {
                int kp   = tid >> 1;
                int half = tid & 1;
                int r    = (kp & 3) * 16 + (kp >> 2);
                const float* ea = emb +
                    (size_t)(chunk * KCHUNK + 2 * kp) * CDIM + c0 + half * 16;
                const float* eb = ea + CDIM;
                float* dst = etd + r * ETD_STRIDE + half * 64;
                #pragma unroll
                for (int c4 = 0; c4 < 4; ++c4) {   // 4 float4 = 16 c
                    float4 a  = *(const float4*)(ea + c4 * 4);
                    float4 bq = *(const float4*)(eb + c4 * 4);
                    *(float4*)(dst + (c4 * 4 + 0) * 4) = make_float4(a.x, a.x, bq.x, bq.x);
                    *(float4*)(dst + (c4 * 4 + 1) * 4) = make_float4(a.y, a.y, bq.y, bq.y);
                    *(float4*)(dst + (c4 * 4 + 2) * 4) = make_float4(a.z, a.z, bq.z, bq.z);
                    *(float4*)(dst + (c4 * 4 + 3) * 4) = make_float4(a.w, a.w, bq.w, bq.w);
                }
            }
            __syncthreads();

            // ---- incremental z_sq (chunk 0 only; exact ascending-c order) --
            if (chunk == 0 && tid < MTILE) {
                int m  = tid;
                int q  = m >> 2;
                int pw = (q >> 1) * 4 + (q & 1) * 32 + (m & 3);
                float s = zsq_sm[m];
                #pragma unroll 8
                for (int c = 0; c < CBLK; ++c) {
                    float v = zt[c * 64 + pw];
                    s = __fadd_rn(s, __fmul_rn(v, v));
                }
                zsq_sm[m] = s;
            }

            // ---- compute: 32 c iters; 6 single-wavefront LDS.128 + 32 FFMA2
            #pragma unroll 2
            for (int c = 0; c < CBLK; ++c) {
                unsigned long long zp[4];
                #pragma unroll
                for (int h = 0; h < 2; ++h) {
                    ulonglong2 zv = *(const ulonglong2*)
                        (zt + c * 64 + tm * 4 + h * 32);
                    zp[2 * h]     = zv.x;          // rows tm*8+4h, +1
                    zp[2 * h + 1] = zv.y;          // rows tm*8+4h+2, +3
                }
                #pragma unroll
                for (int jj = 0; jj < 4; ++jj) {
                    // pair kp = 4*tk + jj  ->  row r = jj*16 + tk
                    ulonglong2 ee = *(const ulonglong2*)
                        (etd + (jj * 16 + tk) * ETD_STRIDE + c * 4);
                    #pragma unroll
                    for (int p = 0; p < 4; ++p) {
                        ffma2(acc[p][2 * jj],     zp[p], ee.x);
                        ffma2(acc[p][2 * jj + 1], zp[p], ee.y);
                    }
                }
            }
        }
        __syncthreads();   // zsq_sm complete (chunk 0); compute done

        // ---- fold chunk into per-thread per-row running argmin -------------
        // d = fl( fl(z_sq + e_sq) - fl(2*e_z) ); ascending chunk/j + strict <
        {
            float esql[8];
            #pragma unroll
            for (int j = 0; j < 8; ++j)
                esql[j] = __ldg(&g_esq[chunk * KCHUNK + tk * 8 + j]);

            #pragma unroll
            for (int p = 0; p < 4; ++p) {
                #pragma unroll
                for (int bb = 0; bb < 2; ++bb) {
                    int i = 2 * p + bb;                 // local row 0..7
                    float zsq = zsq_sm[tm * 8 + i];
                    #pragma unroll
                    for (int j = 0; j < 8; ++j) {
                        float lo, hi; unpack2(acc[p][j], lo, hi);
                        float ez = bb ? hi : lo;
                        float u = __fadd_rn(zsq, esql[j]);
                        float d = __fsub_rn(u, __fmul_rn(2.0f, ez));
                        if (d < best[i]) {
                            best[i] = d;
                            bidx[i] = chunk * KCHUNK + tk * 8 + j;
                        }
                    }
                }
            }
        }
    }

    // ---- single packed-key atomicMin per owned row ---------------------------
    #pragma unroll
    for (int i = 0; i < 8; ++i) {
        int m = tm * 8 + i;
        unsigned u = __float_as_uint(best[i]);
        u = (u & 0x80000000u) ? ~u : (u | 0x80000000u);
        unsigned long long key =
            ((unsigned long long)u << 32) | (unsigned)bidx[i];
        atomicMin(&red[m], key);
    }
    __syncthreads();

    // ---- epilogue: two 32-row passes (gather -> write + loss) ----------------
    float lsum = 0.f;
    float* obase = out + (size_t)b * CDIM * HW + hw0;
    #pragma unroll
    for (int h = 0; h < 2; ++h) {
        // gather: eg[mloc*257 + c] = emb[idx[h*32+mloc]][c]
        #pragma unroll 4
        for (int it = 0; it < 64; ++it) {
            int mloc = it >> 1;
            int cc   = (it & 1) * NTHREADS + tid;
            int kb = (int)(red[h * 32 + mloc] & 0xFFFFFFFFull);
            eg[mloc * 257 + cc] = emb[(size_t)kb * CDIM + cc];
        }
        __syncthreads();

        // write z_q (float4) + loss partial
        #pragma unroll 4
        for (int it = 0; it < 16; ++it) {
            int lin  = it * NTHREADS + tid;     // 2048 float4
            int c    = lin >> 3;
            int m4l  = lin & 7;
            int m4   = h * 8 + m4l;
            float4 zv = *(const float4*)(zbase + (size_t)c * HW + m4 * 4);
            float e0 = eg[(m4l * 4 + 0) * 257 + c];
            float e1 = eg[(m4l * 4 + 1) * 257 + c];
            float e2 = eg[(m4l * 4 + 2) * 257 + c];
            float e3 = eg[(m4l * 4 + 3) * 257 + c];
            float d0 = e0 - zv.x, d1 = e1 - zv.y, d2 = e2 - zv.z, d3 = e3 - zv.w;
            lsum += d0 * d0 + d1 * d1 + d2 * d2 + d3 * d3;
            *(float4*)(obase + (size_t)c * HW + m4 * 4) =
                make_float4(e0, e1, e2, e3);
        }
        __syncthreads();   // eg reads done before next pass overwrites
    }

    // ---- block-reduce loss, atomicAdd global ---------------------------------
    #pragma unroll
    for (int off = 16; off > 0; off >>= 1)
        lsum += __shfl_down_sync(0xFFFFFFFFu, lsum, off);
    if ((tid & 31) == 0) wsum[tid >> 5] = lsum;
    __syncthreads();
    if (tid == 0) {
        float t = wsum[0] + wsum[1] + wsum[2] + wsum[3];
        if (out_size > nz)
            atomicAdd(&out[nz], t * (1.25f / 16777216.0f));  // (1+BETA)*mean
    }
}

// ---------------------------------------------------------------------------
extern "C" void kernel_launch(void* const* d_in, const int* in_sizes, int n_in,
                              void* d_out, int out_size) {
    const float* z   = (const float*)d_in[0];
    const float* emb = (const float*)d_in[1];
    float* out = (float*)d_out;
    const int nz = in_sizes[0];   // 16777216 z_q elements

    static cudaError_t _attr = cudaFuncSetAttribute(
        vq_main_kernel, cudaFuncAttributeMaxDynamicSharedMemorySize, SMEM_BYTES);
    (void)_attr;

    vq_esq_kernel<<<4, 256>>>(emb, out, out_size, nz);
    vq_main_kernel<<<1024, NTHREADS, SMEM_BYTES>>>(z, emb, out, out_size, nz);
}

// round 9
// speedup vs baseline: 1.3727x; 1.3727x over previous
#include <cuda_runtime.h>
#include <cuda_bf16.h>
#include <cstdint>

// Problem constants
#define CDIM   256
#define HW     1024             // 32*32
#define KCODE  1024
#define MTILE  64               // z rows per block
#define KCHUNK 128              // codes per chunk
#define NCHUNK (KCODE / KCHUNK) // 8
#define NTHREADS 256

// dynamic smem (floats):
//   zt : [256 c][64 m] permuted z tile, resident whole kernel = 16384 floats
//   et : 128 code rows x stride 257                           = 32896 floats
// epilogue overlays eg[64*257] = 16448 floats on the same region.
#define ZT_FLOATS   (CDIM * MTILE)         // 16384
#define ET_STRIDE   257
#define ET_FLOATS   (KCHUNK * ET_STRIDE)   // 32896
#define SMEM_FLOATS (ZT_FLOATS + ET_FLOATS)    // 49280
#define SMEM_BYTES  (SMEM_FLOATS * 4)          // 197120 B

__device__ float g_esq[KCODE];

// packed f32x2 FMA: each lane bitwise-identical to fma.rn.f32
__device__ __forceinline__ void ffma2(unsigned long long& acc,
                                      unsigned long long a,
                                      unsigned long long b) {
    asm("fma.rn.f32x2 %0, %1, %2, %0;" : "+l"(acc) : "l"(a), "l"(b));
}
__device__ __forceinline__ unsigned long long splat2(float e) {
    unsigned long long r;
    asm("mov.b64 %0, {%1, %1};" : "=l"(r) : "f"(e));
    return r;
}
__device__ __forceinline__ void unpack2(unsigned long long v, float& lo, float& hi) {
    asm("mov.b64 {%0, %1}, %2;" : "=f"(lo), "=f"(hi) : "l"(v));
}

// ---------------------------------------------------------------------------
// Kernel 0: e_sq[k] = sum_c emb[k][c]^2, SEQUENTIAL fp32 mul-then-add.
// ---------------------------------------------------------------------------
__global__ void vq_esq_kernel(const float* __restrict__ emb,
                              float* __restrict__ out, int out_size, int nz) {
    int k = blockIdx.x * blockDim.x + threadIdx.x;
    if (k < KCODE) {
        const float* e = emb + (size_t)k * CDIM;
        float s = 0.f;
        #pragma unroll 8
        for (int c = 0; c < CDIM; ++c) {
            float v = e[c];
            s = __fadd_rn(s, __fmul_rn(v, v));
        }
        g_esq[k] = s;
    }
    if (blockIdx.x == 0 && threadIdx.x == 0 && out_size > nz)
        out[nz] = 0.0f;
}

// ---------------------------------------------------------------------------
// Main kernel: 256 threads, 1 CTA/SM (8 warps, 2/SMSP). z tile resident
// (permuted, conflict-free); 8 k-chunks of 128 codes via stride-257 et
// (odd stride => per-warp e-rows land on distinct banks; fills use scalar
// STS to respect 4B alignment). Per-thread tile 8 rows x 4 codes.
//   thread map: tm = tid&7 (rows tm*8..+7), tk = tid>>3 (codes tk*4..+3)
//   zt quad q=m>>2 at word (q>>1)*4 + (q&1)*32 (+ m&3)
// ---------------------------------------------------------------------------
__global__ __launch_bounds__(NTHREADS, 1)
void vq_main_kernel(const float* __restrict__ z,
                    const float* __restrict__ emb,
                    float* __restrict__ out, int out_size, int nz) {
    extern __shared__ float smem[];
    float* zt = smem;                  // [c*64 + permuted m]
    float* et = smem + ZT_FLOATS;      // [k*257 + c]
    float* eg = smem;                  // epilogue overlay: [m*257 + c]
    __shared__ unsigned long long red[MTILE];
    __shared__ float zsq_sm[MTILE];
    __shared__ float wsum[8];

    const int tid = threadIdx.x;
    const int tm  = tid & 7;           // 8 row groups of 8
    const int tk  = tid >> 3;          // 32 code groups of 4 (per chunk)
    const int b   = blockIdx.x >> 4;
    const int hw0 = (blockIdx.x & 15) * MTILE;

    const float* zbase = z + (size_t)b * CDIM * HW + hw0;

    if (tid < MTILE) red[tid] = 0xFFFFFFFFFFFFFFFFull;

    // ---- fill zt ONCE: quad m4 -> word (m4>>1)*4 + (m4&1)*32 ---------------
    #pragma unroll
    for (int it = 0; it < 16; ++it) {
        int lin = it * NTHREADS + tid;     // 4096 float4
        int c   = lin >> 4;
        int m4  = lin & 15;
        float4 v = *(const float4*)(zbase + (size_t)c * HW + m4 * 4);
        int pw = (m4 >> 1) * 4 + (m4 & 1) * 32;
        *(float4*)(zt + c * 64 + pw) = v;
    }
    __syncthreads();

    // ---- z_sq per row: SEQUENTIAL fp32, unfused mul+add (exact order) ------
    if (tid < MTILE) {
        int m  = tid;
        int q  = m >> 2;
        int pw = (q >> 1) * 4 + (q & 1) * 32 + (m & 3);
        float s = 0.f;
        #pragma unroll 8
        for (int c = 0; c < CDIM; ++c) {
            float v = zt[c * 64 + pw];
            s = __fadd_rn(s, __fmul_rn(v, v));
        }
        zsq_sm[m] = s;
    }

    float best[8];
    int   bidx[8];
    #pragma unroll
    for (int i = 0; i < 8; ++i) { best[i] = 3.4e38f; bidx[i] = 0; }

    const float* zc = zt + tm * 4;

    for (int chunk = 0; chunk < NCHUNK; ++chunk) {
        __syncthreads();   // prior compute read et; safe to overwrite

        // ---- fill et: [k*257 + c]; float4 LDG, SCALAR STS (odd stride) -----
        const float* ebase = emb + (size_t)chunk * KCHUNK * CDIM;
        #pragma unroll 8
        for (int it = 0; it < 32; ++it) {
            int lin4 = it * NTHREADS + tid;    // 8192 float4
            int k    = lin4 >> 6;
            int c4   = (lin4 & 63) * 4;
            float4 v = *(const float4*)(ebase + k * CDIM + c4);
            float* d = et + k * ET_STRIDE + c4;
            d[0] = v.x; d[1] = v.y; d[2] = v.z; d[3] = v.w;
        }
        __syncthreads();

        // ---- compute: 256 c iters; 2 z LDS.128 + 4 e LDS + 16 FFMA2 -------
        unsigned long long acc[4][4];  // [row-pair p][code j]
        #pragma unroll
        for (int p = 0; p < 4; ++p)
            #pragma unroll
            for (int j = 0; j < 4; ++j) acc[p][j] = 0ull;

        const float* ep = et + tk * 4 * ET_STRIDE;

        #pragma unroll 4
        for (int c = 0; c < CDIM; ++c) {
            ulonglong2 z0 = *(const ulonglong2*)(zc + c * 64);        // rows +0..3
            ulonglong2 z1 = *(const ulonglong2*)(zc + c * 64 + 32);   // rows +4..7
            unsigned long long e0 = splat2(ep[0 * ET_STRIDE + c]);
            unsigned long long e1 = splat2(ep[1 * ET_STRIDE + c]);
            unsigned long long e2 = splat2(ep[2 * ET_STRIDE + c]);
            unsigned long long e3 = splat2(ep[3 * ET_STRIDE + c]);
            ffma2(acc[0][0], z0.x, e0); ffma2(acc[0][1], z0.x, e1);
            ffma2(acc[0][2], z0.x, e2); ffma2(acc[0][3], z0.x, e3);
            ffma2(acc[1][0], z0.y, e0); ffma2(acc[1][1], z0.y, e1);
            ffma2(acc[1][2], z0.y, e2); ffma2(acc[1][3], z0.y, e3);
            ffma2(acc[2][0], z1.x, e0); ffma2(acc[2][1], z1.x, e1);
            ffma2(acc[2][2], z1.x, e2); ffma2(acc[2][3], z1.x, e3);
            ffma2(acc[3][0], z1.y, e0); ffma2(acc[3][1], z1.y, e1);
            ffma2(acc[3][2], z1.y, e2); ffma2(acc[3][3], z1.y, e3);
        }

        // ---- fold chunk into per-thread running argmin ----------------------
        // d = fl( fl(z_sq + e_sq) - fl(2*e_z) ); ascending chunk/j + strict <
        {
            float esql[4];
            #pragma unroll
            for (int j = 0; j < 4; ++j)
                esql[j] = __ldg(&g_esq[chunk * KCHUNK + tk * 4 + j]);

            #pragma unroll
            for (int p = 0; p < 4; ++p) {
                #pragma unroll
                for (int bb = 0; bb < 2; ++bb) {
                    int i = 2 * p + bb;                 // local row 0..7
                    float zsq = zsq_sm[tm * 8 + i];
                    #pragma unroll
                    for (int j = 0; j < 4; ++j) {
                        float lo, hi; unpack2(acc[p][j], lo, hi);
                        float ez = bb ? hi : lo;
                        float u = __fadd_rn(zsq, esql[j]);
                        float d = __fsub_rn(u, __fmul_rn(2.0f, ez));
                        if (d < best[i]) {
                            best[i] = d;
                            bidx[i] = chunk * KCHUNK + tk * 4 + j;
                        }
                    }
                }
            }
        }
    }

    // ---- single packed-key atomicMin per owned row ---------------------------
    #pragma unroll
    for (int i = 0; i < 8; ++i) {
        int m = tm * 8 + i;
        unsigned u = __float_as_uint(best[i]);
        u = (u & 0x80000000u) ? ~u : (u | 0x80000000u);
        unsigned long long key =
            ((unsigned long long)u << 32) | (unsigned)bidx[i];
        atomicMin(&red[m], key);
    }
    __syncthreads();

    // ---- gather: eg[m*257 + c] = emb[idx[m]][c] (coalesced rows) -------------
    #pragma unroll 4
    for (int m = 0; m < MTILE; ++m) {
        int kb = (int)(red[m] & 0xFFFFFFFFull);
        eg[m * 257 + tid] = emb[(size_t)kb * CDIM + tid];
    }
    __syncthreads();

    // ---- write z_q (float4) + loss partial (z re-read from gmem) -------------
    float lsum = 0.f;
    float* obase = out + (size_t)b * CDIM * HW + hw0;
    #pragma unroll 4
    for (int it = 0; it < 16; ++it) {
        int lin = it * NTHREADS + tid;       // 4096 float4
        int c   = lin >> 4;
        int m4  = lin & 15;
        float4 zv = *(const float4*)(zbase + (size_t)c * HW + m4 * 4);
        float e0 = eg[(m4 * 4 + 0) * 257 + c];
        float e1 = eg[(m4 * 4 + 1) * 257 + c];
        float e2 = eg[(m4 * 4 + 2) * 257 + c];
        float e3 = eg[(m4 * 4 + 3) * 257 + c];
        float d0 = e0 - zv.x, d1 = e1 - zv.y, d2 = e2 - zv.z, d3 = e3 - zv.w;
        lsum += d0 * d0 + d1 * d1 + d2 * d2 + d3 * d3;
        *(float4*)(obase + (size_t)c * HW + m4 * 4) = make_float4(e0, e1, e2, e3);
    }

    // ---- block-reduce loss, atomicAdd global ---------------------------------
    #pragma unroll
    for (int off = 16; off > 0; off >>= 1)
        lsum += __shfl_down_sync(0xFFFFFFFFu, lsum, off);
    if ((tid & 31) == 0) wsum[tid >> 5] = lsum;
    __syncthreads();
    if (tid == 0) {
        float t = 0.f;
        #pragma unroll
        for (int w = 0; w < 8; ++w) t += wsum[w];
        if (out_size > nz)
            atomicAdd(&out[nz], t * (1.25f / 16777216.0f));  // (1+BETA)*mean
    }
}

// ---------------------------------------------------------------------------
extern "C" void kernel_launch(void* const* d_in, const int* in_sizes, int n_in,
                              void* d_out, int out_size) {
    const float* z   = (const float*)d_in[0];
    const float* emb = (const float*)d_in[1];
    float* out = (float*)d_out;
    const int nz = in_sizes[0];   // 16777216 z_q elements

    static cudaError_t _attr = cudaFuncSetAttribute(
        vq_main_kernel, cudaFuncAttributeMaxDynamicSharedMemorySize, SMEM_BYTES);
    (void)_attr;

    vq_esq_kernel<<<4, 256>>>(emb, out, out_size, nz);
    vq_main_kernel<<<1024, NTHREADS, SMEM_BYTES>>>(z, emb, out, out_size, nz);
}